// round 12
// baseline (speedup 1.0000x reference)
#include <cuda_runtime.h>
#include <cuda_bf16.h>
#include <cstdint>

// Problem constants
#define BB   4
#define TT   2048
#define NC   4096
#define AA   8
#define SINK_ITERS 20
#define EPS_ 1e-5f

// tensor-core logits tiling
#define TOKCTA 64              // tokens per CTA
#define KSPLIT 16
#define DK     (NC / KSPLIT)   // 256 d per CTA
#define NTILES 128             // token tiles (8192/64)
#define ASTR   264             // A smem row stride (bf16 els): banks 4g+t all-distinct
#define BSTR   264             // B smem row stride
#define PARTW  28              // partial row: 24 logits + ssq + pad

// smem layout (ushort units)
#define A_HI_OFF 0
#define A_LO_OFF (TOKCTA * ASTR)                 // 16896
#define B_HI_OFF (2 * TOKCTA * ASTR)             // 33792
#define B_LO_OFF (B_HI_OFF + 24 * BSTR)          // 40128
#define SM_USHORTS (B_LO_OFF + 24 * BSTR)        // 46464
#define SMEM_TC_BYTES (SM_USHORTS * 2 + TOKCTA * 2 * 4)   // + ssq floats = 93440

// ---------------- scratch ----------------
__device__ __align__(16) unsigned short g_hi[AA * 24 * NC];         // phi hi (bf16), [a][k][d]
__device__ __align__(16) unsigned short g_lo[AA * 24 * NC];         // phi lo residual
__device__ __align__(16) float part_buf[KSPLIT * BB * TT * PARTW];  // 14.7 MB
__device__ __align__(16) float W_buf[BB * TT * 16];

// ---------------- helpers ----------------
__device__ __forceinline__ void cp16(uint32_t dst, const void* src) {
    asm volatile("cp.async.cg.shared.global [%0], [%1], 16;" :: "r"(dst), "l"(src));
}
__device__ __forceinline__ void mma_bf16(float* c, uint32_t a0, uint32_t a1, uint32_t a2,
                                         uint32_t a3, uint32_t b0, uint32_t b1) {
    asm volatile("mma.sync.aligned.m16n8k16.row.col.f32.bf16.bf16.f32 "
                 "{%0,%1,%2,%3}, {%4,%5,%6,%7}, {%8,%9}, {%0,%1,%2,%3};"
                 : "+f"(c[0]), "+f"(c[1]), "+f"(c[2]), "+f"(c[3])
                 : "r"(a0), "r"(a1), "r"(a2), "r"(a3), "r"(b0), "r"(b1));
}
__device__ __forceinline__ uint32_t pack_bf16_hi(float v0, float v1, float& r0, float& r1) {
    __nv_bfloat16 h0 = __float2bfloat16(v0);
    __nv_bfloat16 h1 = __float2bfloat16(v1);
    r0 = v0 - __bfloat162float(h0);
    r1 = v1 - __bfloat162float(h1);
    return (uint32_t)__bfloat16_as_ushort(h0) | ((uint32_t)__bfloat16_as_ushort(h1) << 16);
}
__device__ __forceinline__ uint32_t pack_bf16(float v0, float v1) {
    return (uint32_t)__bfloat16_as_ushort(__float2bfloat16(v0))
         | ((uint32_t)__bfloat16_as_ushort(__float2bfloat16(v1)) << 16);
}

// ---------------- kernel 1: fold alpha*w*phi -> bf16 hi/lo, [a][k][4096] ----------------
__global__ void fold_tc(const float* __restrict__ wnorm,
                        const float* __restrict__ ppre, const float* __restrict__ ppost,
                        const float* __restrict__ pres,
                        const float* __restrict__ apre, const float* __restrict__ apost,
                        const float* __restrict__ ares) {
    const int a = blockIdx.x / 24, k = blockIdx.x % 24;
    const float alpha = (k < 4) ? apre[a] : (k < 8) ? apost[a] : ares[a];
#pragma unroll 4
    for (int j = 0; j < 16; ++j) {
        int d = j * 256 + threadIdx.x;
        int ad = a * NC + d;
        float coef = alpha * wnorm[ad];
        float val;
        if (k < 4)      val = ppre[(size_t)ad * 4 + k];
        else if (k < 8) val = ppost[(size_t)ad * 4 + (k - 4)];
        else            val = pres[(size_t)ad * 16 + (k - 8)];
        val *= coef;
        __nv_bfloat16 h = __float2bfloat16(val);
        float lo = val - __bfloat162float(h);
        size_t o = (size_t)(a * 24 + k) * NC + d;
        g_hi[o] = __bfloat16_as_ushort(h);
        g_lo[o] = __bfloat16_as_ushort(__float2bfloat16(lo));
    }
}

// ---------------- kernel 2: logits via mma.sync m16n8k16 bf16 (hi/lo split) ----------------
// grid = 2048: blockIdx.x = tt*KSPLIT + ks. 128 threads = 4 warps, warp -> 16 tokens.
__global__ void __launch_bounds__(128, 2)
logits_tc(const float* __restrict__ x, const int* __restrict__ aidx) {
    extern __shared__ __align__(16) unsigned short sm[];
    unsigned short* Ah = sm + A_HI_OFF;
    unsigned short* Al = sm + A_LO_OFF;
    unsigned short* Bh = sm + B_HI_OFF;
    unsigned short* Bl = sm + B_LO_OFF;
    float* ssqp = (float*)(sm + SM_USHORTS);      // [64][2]

    const int tid = threadIdx.x;
    const int ks = blockIdx.x & (KSPLIT - 1);
    const int tt = blockIdx.x >> 4;               // 0..127
    const int t0 = tt * TOKCTA;
    const int aid = aidx[t0 >> 11];

    // ---- B (phi hi/lo) via cp.async: 24 rows x 256 els x 2B each ----
    uint32_t sb = (uint32_t)__cvta_generic_to_shared(sm);
#pragma unroll
    for (int i = 0; i < 6; ++i) {
        int f = i * 128 + tid;                    // 0..767
        int n = f >> 5, c = f & 31;               // 16B chunk = 8 els
        size_t src = (size_t)(aid * 24 + n) * NC + ks * DK + c * 8;
        cp16(sb + (B_HI_OFF + n * BSTR + c * 8) * 2, g_hi + src);
        cp16(sb + (B_LO_OFF + n * BSTR + c * 8) * 2, g_lo + src);
    }
    asm volatile("cp.async.commit_group;");

    // ---- A: load x fp32, split to bf16 hi/lo, exact fp32 ssq ----
    {
        const int row = tid >> 1, h = tid & 1;    // thread owns half a token row
        const float4* xp = (const float4*)(x + (size_t)(t0 + row) * NC + ks * DK + h * 128);
        unsigned short* arh = Ah + row * ASTR + h * 128;
        unsigned short* arl = Al + row * ASTR + h * 128;
        float ssq = 0.0f;
#pragma unroll 8
        for (int j = 0; j < 32; ++j) {
            float4 v = xp[j];
            ssq += v.x * v.x + v.y * v.y + v.z * v.z + v.w * v.w;
            float r0, r1, r2, r3;
            uint32_t h01 = pack_bf16_hi(v.x, v.y, r0, r1);
            uint32_t h23 = pack_bf16_hi(v.z, v.w, r2, r3);
            uint32_t l01 = pack_bf16(r0, r1);
            uint32_t l23 = pack_bf16(r2, r3);
            *(uint2*)(arh + j * 4) = make_uint2(h01, h23);
            *(uint2*)(arl + j * 4) = make_uint2(l01, l23);
        }
        ssqp[row * 2 + h] = ssq;
    }

    asm volatile("cp.async.wait_group 0;");
    __syncthreads();

    // ---- mma mainloop ----
    const int warp = tid >> 5, lane = tid & 31;
    const int g = lane >> 2, t = lane & 3;
    const int grow = warp * 16;

    float acc[3][4];
#pragma unroll
    for (int nt = 0; nt < 3; ++nt)
#pragma unroll
        for (int q = 0; q < 4; ++q) acc[nt][q] = 0.0f;

    const unsigned short* ArH  = Ah + (grow + g) * ASTR + 2 * t;
    const unsigned short* ArH8 = ArH + 8 * ASTR;
    const unsigned short* ArL  = Al + (grow + g) * ASTR + 2 * t;
    const unsigned short* ArL8 = ArL + 8 * ASTR;

#pragma unroll 4
    for (int kc = 0; kc < 16; ++kc) {
        const int k0 = kc * 16;
        uint32_t ah0 = *(const uint32_t*)(ArH  + k0);
        uint32_t ah1 = *(const uint32_t*)(ArH8 + k0);
        uint32_t ah2 = *(const uint32_t*)(ArH  + k0 + 8);
        uint32_t ah3 = *(const uint32_t*)(ArH8 + k0 + 8);
        uint32_t al0 = *(const uint32_t*)(ArL  + k0);
        uint32_t al1 = *(const uint32_t*)(ArL8 + k0);
        uint32_t al2 = *(const uint32_t*)(ArL  + k0 + 8);
        uint32_t al3 = *(const uint32_t*)(ArL8 + k0 + 8);
#pragma unroll
        for (int nt = 0; nt < 3; ++nt) {
            const unsigned short* brh = Bh + (nt * 8 + g) * BSTR + 2 * t + k0;
            const unsigned short* brl = Bl + (nt * 8 + g) * BSTR + 2 * t + k0;
            uint32_t bh0 = *(const uint32_t*)(brh);
            uint32_t bh1 = *(const uint32_t*)(brh + 8);
            uint32_t bl0 = *(const uint32_t*)(brl);
            uint32_t bl1 = *(const uint32_t*)(brl + 8);
            mma_bf16(acc[nt], ah0, ah1, ah2, ah3, bh0, bh1);   // hi*hi
            mma_bf16(acc[nt], ah0, ah1, ah2, ah3, bl0, bl1);   // hi*lo
            mma_bf16(acc[nt], al0, al1, al2, al3, bh0, bh1);   // lo*hi
        }
    }

    // ---- epilogue: D rows = tokens directly; no shuffles ----
    const int r1 = t0 + grow + g, r2 = r1 + 8;
    float* p1 = part_buf + ((size_t)ks * (BB * TT) + r1) * PARTW;
    float* p2 = part_buf + ((size_t)ks * (BB * TT) + r2) * PARTW;
#pragma unroll
    for (int nt = 0; nt < 3; ++nt) {
        *(float2*)(p1 + nt * 8 + 2 * t) = make_float2(acc[nt][0], acc[nt][1]);
        *(float2*)(p2 + nt * 8 + 2 * t) = make_float2(acc[nt][2], acc[nt][3]);
    }
    if (t == 0) {
        const int lr = grow + g;
        p1[24] = ssqp[lr * 2] + ssqp[lr * 2 + 1];
        p2[24] = ssqp[(lr + 8) * 2] + ssqp[(lr + 8) * 2 + 1];
    }
}

// ---------------- kernel 3: finalize (reduce 16 splits, sinkhorn -> W) ----------------
__global__ void finalize_k(const float* __restrict__ bpre, const float* __restrict__ bpost,
                           const float* __restrict__ bres, const int* __restrict__ aidx) {
    const int t = blockIdx.x * 128 + threadIdx.x;
    const int aid = aidx[t >> 11];

    float a[24];
#pragma unroll
    for (int k = 0; k < 24; ++k) a[k] = 0.0f;
    float ssq = 0.0f;
#pragma unroll 8
    for (int ks = 0; ks < KSPLIT; ++ks) {
        const float4* p = (const float4*)(part_buf + ((size_t)ks * (BB * TT) + t) * PARTW);
#pragma unroll
        for (int q = 0; q < 6; ++q) {
            float4 v = p[q];
            a[q * 4 + 0] += v.x; a[q * 4 + 1] += v.y;
            a[q * 4 + 2] += v.z; a[q * 4 + 3] += v.w;
        }
        ssq += p[6].x;
    }
    float rinv = rsqrtf(ssq * (1.0f / 4096.0f) + EPS_);

    float hpre[4], hpost[4];
#pragma unroll
    for (int n = 0; n < 4; ++n)
        hpre[n] = 1.0f / (1.0f + expf(-(a[n] * rinv + bpre[aid * 4 + n])));
#pragma unroll
    for (int n = 0; n < 4; ++n)
        hpost[n] = 2.0f / (1.0f + expf(-(a[4 + n] * rinv + bpost[aid * 4 + n])));

    float m[16];
#pragma unroll
    for (int ij = 0; ij < 16; ++ij)
        m[ij] = expf(a[8 + ij] * rinv + bres[aid * 16 + ij]);

    for (int it = 0; it < SINK_ITERS; ++it) {
#pragma unroll
        for (int i = 0; i < 4; ++i) {
            float r = 1.0f / (m[i * 4] + m[i * 4 + 1] + m[i * 4 + 2] + m[i * 4 + 3]);
            m[i * 4] *= r; m[i * 4 + 1] *= r; m[i * 4 + 2] *= r; m[i * 4 + 3] *= r;
        }
#pragma unroll
        for (int j = 0; j < 4; ++j) {
            float r = 1.0f / (m[j] + m[4 + j] + m[8 + j] + m[12 + j]);
            m[j] *= r; m[4 + j] *= r; m[8 + j] *= r; m[12 + j] *= r;
        }
    }

    float4* wd = (float4*)(W_buf + (size_t)t * 16);
#pragma unroll
    for (int i = 0; i < 4; ++i)
        wd[i] = make_float4(m[i * 4 + 0] + hpost[i] * hpre[0],
                            m[i * 4 + 1] + hpost[i] * hpre[1],
                            m[i * 4 + 2] + hpost[i] * hpre[2],
                            m[i * 4 + 3] + hpost[i] * hpre[3]);
}

// ---------------- kernel 4: out[token] = W @ x[token] ----------------
__global__ void out_k(const float* __restrict__ x, float* __restrict__ out) {
    const int token = (BB * TT - 1) - blockIdx.x;
    __shared__ float sW[16];
    if (threadIdx.x < 16) sW[threadIdx.x] = W_buf[(size_t)token * 16 + threadIdx.x];
    __syncthreads();
    const float4* xr = (const float4*)(x + (size_t)token * NC);
    float4* orow = (float4*)(out + (size_t)token * NC);
    const int c = threadIdx.x;
    float4 xv0 = xr[c], xv1 = xr[256 + c], xv2 = xr[512 + c], xv3 = xr[768 + c];
#pragma unroll
    for (int i = 0; i < 4; ++i) {
        float w0 = sW[i * 4], w1 = sW[i * 4 + 1], w2 = sW[i * 4 + 2], w3 = sW[i * 4 + 3];
        float4 o;
        o.x = w0 * xv0.x + w1 * xv1.x + w2 * xv2.x + w3 * xv3.x;
        o.y = w0 * xv0.y + w1 * xv1.y + w2 * xv2.y + w3 * xv3.y;
        o.z = w0 * xv0.z + w1 * xv1.z + w2 * xv2.z + w3 * xv3.z;
        o.w = w0 * xv0.w + w1 * xv1.w + w2 * xv2.w + w3 * xv3.w;
        orow[i * 256 + c] = o;
    }
}

// ---------------- launch ----------------
extern "C" void kernel_launch(void* const* d_in, const int* in_sizes, int n_in,
                              void* d_out, int out_size) {
    const float* x     = (const float*)d_in[0];
    const float* wnorm = (const float*)d_in[1];
    const float* ppre  = (const float*)d_in[2];
    const float* ppost = (const float*)d_in[3];
    const float* pres  = (const float*)d_in[4];
    const float* bpre  = (const float*)d_in[5];
    const float* bpost = (const float*)d_in[6];
    const float* bres  = (const float*)d_in[7];
    const float* apre  = (const float*)d_in[8];
    const float* apost = (const float*)d_in[9];
    const float* ares  = (const float*)d_in[10];
    const int*   aidx  = (const int*)d_in[11];
    float* out = (float*)d_out;

    cudaFuncSetAttribute(logits_tc, cudaFuncAttributeMaxDynamicSharedMemorySize, SMEM_TC_BYTES);

    fold_tc<<<AA * 24, 256>>>(wnorm, ppre, ppost, pres, apre, apost, ares);
    logits_tc<<<NTILES * KSPLIT, 128, SMEM_TC_BYTES>>>(x, aidx);
    finalize_k<<<BB * TT / 128, 128>>>(bpre, bpost, bres, aidx);
    out_k<<<BB * TT, 256>>>(x, out);
}

// round 13
// speedup vs baseline: 1.0850x; 1.0850x over previous
#include <cuda_runtime.h>
#include <cuda_bf16.h>
#include <cstdint>

// Problem constants
#define BB   4
#define TT   2048
#define NC   4096
#define AA   8
#define SINK_ITERS 20
#define EPS_ 1e-5f

// tensor-core logits tiling v2
#define TOKCTA 64              // tokens per CTA
#define KSPLIT 32
#define DK     (NC / KSPLIT)   // 128 d per CTA
#define NTILES 128             // token tiles (8192/64)
#define ASTR   136             // A smem row stride (ushorts): banks 4g+t all-distinct
#define BSTR   136
#define PARTW  28              // partial row: 24 logits + ssq + pad
#define NKC    (DK / 16)       // 8 mma k-chunks

// smem layout (ushort units)
#define A_HI_OFF 0
#define A_LO_OFF (TOKCTA * ASTR)                 // 8704
#define B_HI_OFF (2 * TOKCTA * ASTR)             // 17408
#define B_LO_OFF (B_HI_OFF + 24 * BSTR)          // 20672
#define SM_USHORTS (B_LO_OFF + 24 * BSTR)        // 23936  (47872 B + ssq = 48128 B)

// ---------------- scratch ----------------
__device__ __align__(16) unsigned short g_hi[AA * 24 * NC];         // phi hi (bf16), [a][k][d]
__device__ __align__(16) unsigned short g_lo[AA * 24 * NC];         // phi lo residual
__device__ __align__(16) float part_buf[KSPLIT * BB * TT * PARTW];  // 29.4 MB
__device__ __align__(16) float W_buf[BB * TT * 16];

// ---------------- helpers ----------------
__device__ __forceinline__ void cp16(uint32_t dst, const void* src) {
    asm volatile("cp.async.cg.shared.global [%0], [%1], 16;" :: "r"(dst), "l"(src));
}
__device__ __forceinline__ void mma_bf16(float* c, uint32_t a0, uint32_t a1, uint32_t a2,
                                         uint32_t a3, uint32_t b0, uint32_t b1) {
    asm volatile("mma.sync.aligned.m16n8k16.row.col.f32.bf16.bf16.f32 "
                 "{%0,%1,%2,%3}, {%4,%5,%6,%7}, {%8,%9}, {%0,%1,%2,%3};"
                 : "+f"(c[0]), "+f"(c[1]), "+f"(c[2]), "+f"(c[3])
                 : "r"(a0), "r"(a1), "r"(a2), "r"(a3), "r"(b0), "r"(b1));
}
__device__ __forceinline__ uint32_t cvt_bf16x2(float hi, float lo) {
    uint32_t d;
    asm("cvt.rn.bf16x2.f32 %0, %1, %2;" : "=r"(d) : "f"(hi), "f"(lo));
    return d;
}

// ---------------- kernel 1: fold alpha*w*phi -> bf16 hi/lo, [a][k][4096] ----------------
__global__ void fold_tc(const float* __restrict__ wnorm,
                        const float* __restrict__ ppre, const float* __restrict__ ppost,
                        const float* __restrict__ pres,
                        const float* __restrict__ apre, const float* __restrict__ apost,
                        const float* __restrict__ ares) {
    const int a = blockIdx.x / 24, k = blockIdx.x % 24;
    const float alpha = (k < 4) ? apre[a] : (k < 8) ? apost[a] : ares[a];
#pragma unroll 4
    for (int j = 0; j < 16; ++j) {
        int d = j * 256 + threadIdx.x;
        int ad = a * NC + d;
        float coef = alpha * wnorm[ad];
        float val;
        if (k < 4)      val = ppre[(size_t)ad * 4 + k];
        else if (k < 8) val = ppost[(size_t)ad * 4 + (k - 4)];
        else            val = pres[(size_t)ad * 16 + (k - 8)];
        val *= coef;
        __nv_bfloat16 h = __float2bfloat16(val);
        float lo = val - __bfloat162float(h);
        size_t o = (size_t)(a * 24 + k) * NC + d;
        g_hi[o] = __bfloat16_as_ushort(h);
        g_lo[o] = __bfloat16_as_ushort(__float2bfloat16(lo));
    }
}

// ---------------- kernel 2: logits via mma.sync bf16 hi/lo, v2 ----------------
// grid = 4096: blockIdx.x = tt*KSPLIT + ks. 128 threads = 4 warps; warp w -> rows w*16..w*16+15.
__global__ void __launch_bounds__(128, 4)
logits_tc(const float* __restrict__ x, const int* __restrict__ aidx) {
    __shared__ __align__(16) unsigned short sm[SM_USHORTS];
    __shared__ float ssqs[TOKCTA];

    unsigned short* Ah = sm + A_HI_OFF;
    unsigned short* Al = sm + A_LO_OFF;
    unsigned short* Bh = sm + B_HI_OFF;
    unsigned short* Bl = sm + B_LO_OFF;

    const int tid = threadIdx.x;
    const int ks = blockIdx.x & (KSPLIT - 1);
    const int tt = blockIdx.x >> 5;               // 0..127
    const int t0 = tt * TOKCTA;
    const int aid = aidx[t0 >> 11];
    const int warp = tid >> 5, lane = tid & 31;

    // ---- B (phi hi/lo) via cp.async: 24 rows x 128 els -> 384 16B chunks per buffer ----
    uint32_t sb = (uint32_t)__cvta_generic_to_shared(sm);
#pragma unroll
    for (int i = 0; i < 3; ++i) {
        int f = i * 128 + tid;                    // 0..383
        int n = f >> 4, c = f & 15;
        size_t src = (size_t)(aid * 24 + n) * NC + ks * DK + c * 8;
        cp16(sb + (B_HI_OFF + n * BSTR + c * 8) * 2, g_hi + src);
        cp16(sb + (B_LO_OFF + n * BSTR + c * 8) * 2, g_lo + src);
    }
    asm volatile("cp.async.commit_group;");

    // ---- A: coalesced x load (warp = one 512B row segment), truncation split ----
    {
        const float* xbase = x + (size_t)t0 * NC + ks * DK;
#pragma unroll 4
        for (int r = 0; r < 16; ++r) {
            const int row = warp * 16 + r;
            float4 v = *((const float4*)(xbase + (size_t)row * NC) + lane);
            float ps = v.x * v.x + v.y * v.y + v.z * v.z + v.w * v.w;

            uint32_t u0 = __float_as_uint(v.x), u1 = __float_as_uint(v.y);
            uint32_t u2 = __float_as_uint(v.z), u3 = __float_as_uint(v.w);
            uint32_t h01 = __byte_perm(u0, u1, 0x7632);   // hi16(v.y)|hi16(v.x)
            uint32_t h23 = __byte_perm(u2, u3, 0x7632);
            float f0 = __uint_as_float(u0 & 0xffff0000u);
            float f1 = __uint_as_float(u1 & 0xffff0000u);
            float f2 = __uint_as_float(u2 & 0xffff0000u);
            float f3 = __uint_as_float(u3 & 0xffff0000u);
            uint32_t l01 = cvt_bf16x2(v.y - f1, v.x - f0);
            uint32_t l23 = cvt_bf16x2(v.w - f3, v.z - f2);

            *(uint2*)(Ah + row * ASTR + lane * 4) = make_uint2(h01, h23);
            *(uint2*)(Al + row * ASTR + lane * 4) = make_uint2(l01, l23);

#pragma unroll
            for (int m = 1; m < 32; m <<= 1)
                ps += __shfl_xor_sync(0xffffffffu, ps, m);
            if (lane == 0) ssqs[row] = ps;
        }
    }

    asm volatile("cp.async.wait_group 0;");
    __syncthreads();

    // ---- mma mainloop (fragment mapping verified in R12) ----
    const int g = lane >> 2, t = lane & 3;
    const int grow = warp * 16;

    float acc[3][4];
#pragma unroll
    for (int nt = 0; nt < 3; ++nt)
#pragma unroll
        for (int q = 0; q < 4; ++q) acc[nt][q] = 0.0f;

    const unsigned short* ArH  = Ah + (grow + g) * ASTR + 2 * t;
    const unsigned short* ArH8 = ArH + 8 * ASTR;
    const unsigned short* ArL  = Al + (grow + g) * ASTR + 2 * t;
    const unsigned short* ArL8 = ArL + 8 * ASTR;

#pragma unroll
    for (int kc = 0; kc < NKC; ++kc) {
        const int k0 = kc * 16;
        uint32_t ah0 = *(const uint32_t*)(ArH  + k0);
        uint32_t ah1 = *(const uint32_t*)(ArH8 + k0);
        uint32_t ah2 = *(const uint32_t*)(ArH  + k0 + 8);
        uint32_t ah3 = *(const uint32_t*)(ArH8 + k0 + 8);
        uint32_t al0 = *(const uint32_t*)(ArL  + k0);
        uint32_t al1 = *(const uint32_t*)(ArL8 + k0);
        uint32_t al2 = *(const uint32_t*)(ArL  + k0 + 8);
        uint32_t al3 = *(const uint32_t*)(ArL8 + k0 + 8);
#pragma unroll
        for (int nt = 0; nt < 3; ++nt) {
            const unsigned short* brh = Bh + (nt * 8 + g) * BSTR + 2 * t + k0;
            const unsigned short* brl = Bl + (nt * 8 + g) * BSTR + 2 * t + k0;
            uint32_t bh0 = *(const uint32_t*)(brh);
            uint32_t bh1 = *(const uint32_t*)(brh + 8);
            uint32_t bl0 = *(const uint32_t*)(brl);
            uint32_t bl1 = *(const uint32_t*)(brl + 8);
            mma_bf16(acc[nt], ah0, ah1, ah2, ah3, bh0, bh1);   // hi*hi
            mma_bf16(acc[nt], ah0, ah1, ah2, ah3, bl0, bl1);   // hi*lo
            mma_bf16(acc[nt], al0, al1, al2, al3, bh0, bh1);   // lo*hi
        }
    }

    // ---- epilogue: D rows = tokens directly ----
    const int r1 = t0 + grow + g, r2 = r1 + 8;
    float* p1 = part_buf + ((size_t)ks * (BB * TT) + r1) * PARTW;
    float* p2 = part_buf + ((size_t)ks * (BB * TT) + r2) * PARTW;
#pragma unroll
    for (int nt = 0; nt < 3; ++nt) {
        *(float2*)(p1 + nt * 8 + 2 * t) = make_float2(acc[nt][0], acc[nt][1]);
        *(float2*)(p2 + nt * 8 + 2 * t) = make_float2(acc[nt][2], acc[nt][3]);
    }
    if (t == 0) {
        p1[24] = ssqs[grow + g];
        p2[24] = ssqs[grow + g + 8];
    }
}

// ---------------- kernel 3: finalize (reduce 32 splits, sinkhorn -> W) ----------------
__global__ void finalize_k(const float* __restrict__ bpre, const float* __restrict__ bpost,
                           const float* __restrict__ bres, const int* __restrict__ aidx) {
    const int t = blockIdx.x * 128 + threadIdx.x;
    const int aid = aidx[t >> 11];

    float a[24];
#pragma unroll
    for (int k = 0; k < 24; ++k) a[k] = 0.0f;
    float ssq = 0.0f;
#pragma unroll 8
    for (int ks = 0; ks < KSPLIT; ++ks) {
        const float4* p = (const float4*)(part_buf + ((size_t)ks * (BB * TT) + t) * PARTW);
#pragma unroll
        for (int q = 0; q < 6; ++q) {
            float4 v = p[q];
            a[q * 4 + 0] += v.x; a[q * 4 + 1] += v.y;
            a[q * 4 + 2] += v.z; a[q * 4 + 3] += v.w;
        }
        ssq += p[6].x;
    }
    float rinv = rsqrtf(ssq * (1.0f / 4096.0f) + EPS_);

    float hpre[4], hpost[4];
#pragma unroll
    for (int n = 0; n < 4; ++n)
        hpre[n] = 1.0f / (1.0f + expf(-(a[n] * rinv + bpre[aid * 4 + n])));
#pragma unroll
    for (int n = 0; n < 4; ++n)
        hpost[n] = 2.0f / (1.0f + expf(-(a[4 + n] * rinv + bpost[aid * 4 + n])));

    float m[16];
#pragma unroll
    for (int ij = 0; ij < 16; ++ij)
        m[ij] = expf(a[8 + ij] * rinv + bres[aid * 16 + ij]);

    for (int it = 0; it < SINK_ITERS; ++it) {
#pragma unroll
        for (int i = 0; i < 4; ++i) {
            float r = 1.0f / (m[i * 4] + m[i * 4 + 1] + m[i * 4 + 2] + m[i * 4 + 3]);
            m[i * 4] *= r; m[i * 4 + 1] *= r; m[i * 4 + 2] *= r; m[i * 4 + 3] *= r;
        }
#pragma unroll
        for (int j = 0; j < 4; ++j) {
            float r = 1.0f / (m[j] + m[4 + j] + m[8 + j] + m[12 + j]);
            m[j] *= r; m[4 + j] *= r; m[8 + j] *= r; m[12 + j] *= r;
        }
    }

    float4* wd = (float4*)(W_buf + (size_t)t * 16);
#pragma unroll
    for (int i = 0; i < 4; ++i)
        wd[i] = make_float4(m[i * 4 + 0] + hpost[i] * hpre[0],
                            m[i * 4 + 1] + hpost[i] * hpre[1],
                            m[i * 4 + 2] + hpost[i] * hpre[2],
                            m[i * 4 + 3] + hpost[i] * hpre[3]);
}

// ---------------- kernel 4: out[token] = W @ x[token] ----------------
__global__ void out_k(const float* __restrict__ x, float* __restrict__ out) {
    const int token = (BB * TT - 1) - blockIdx.x;
    __shared__ float sW[16];
    if (threadIdx.x < 16) sW[threadIdx.x] = W_buf[(size_t)token * 16 + threadIdx.x];
    __syncthreads();
    const float4* xr = (const float4*)(x + (size_t)token * NC);
    float4* orow = (float4*)(out + (size_t)token * NC);
    const int c = threadIdx.x;
    float4 xv0 = xr[c], xv1 = xr[256 + c], xv2 = xr[512 + c], xv3 = xr[768 + c];
#pragma unroll
    for (int i = 0; i < 4; ++i) {
        float w0 = sW[i * 4], w1 = sW[i * 4 + 1], w2 = sW[i * 4 + 2], w3 = sW[i * 4 + 3];
        float4 o;
        o.x = w0 * xv0.x + w1 * xv1.x + w2 * xv2.x + w3 * xv3.x;
        o.y = w0 * xv0.y + w1 * xv1.y + w2 * xv2.y + w3 * xv3.y;
        o.z = w0 * xv0.z + w1 * xv1.z + w2 * xv2.z + w3 * xv3.z;
        o.w = w0 * xv0.w + w1 * xv1.w + w2 * xv2.w + w3 * xv3.w;
        orow[i * 256 + c] = o;
    }
}

// ---------------- launch ----------------
extern "C" void kernel_launch(void* const* d_in, const int* in_sizes, int n_in,
                              void* d_out, int out_size) {
    const float* x     = (const float*)d_in[0];
    const float* wnorm = (const float*)d_in[1];
    const float* ppre  = (const float*)d_in[2];
    const float* ppost = (const float*)d_in[3];
    const float* pres  = (const float*)d_in[4];
    const float* bpre  = (const float*)d_in[5];
    const float* bpost = (const float*)d_in[6];
    const float* bres  = (const float*)d_in[7];
    const float* apre  = (const float*)d_in[8];
    const float* apost = (const float*)d_in[9];
    const float* ares  = (const float*)d_in[10];
    const int*   aidx  = (const int*)d_in[11];
    float* out = (float*)d_out;

    fold_tc<<<AA * 24, 256>>>(wnorm, ppre, ppost, pres, apre, apost, ares);
    logits_tc<<<NTILES * KSPLIT, 128>>>(x, aidx);
    finalize_k<<<BB * TT / 128, 128>>>(bpre, bpost, bres, aidx);
    out_k<<<BB * TT, 256>>>(x, out);
}

// round 14
// speedup vs baseline: 1.1511x; 1.0609x over previous
#include <cuda_runtime.h>
#include <cuda_bf16.h>
#include <cstdint>

// Problem constants
#define BB   4
#define TT   2048
#define NC   4096
#define AA   8
#define SINK_ITERS 20
#define EPS_ 1e-5f

// tensor-core logits tiling v3
#define TOKCTA 64              // tokens per CTA
#define KSPLIT 32
#define DK     (NC / KSPLIT)   // 128 d per CTA
#define NTILES 128             // token tiles (8192/64)
#define ASTR   136             // A smem row stride (ushorts): banks 4g+t all-distinct
#define BSTR   136
#define PARTW  28              // partial row: 24 logits + ssq + pad
#define NKC    (DK / 16)       // 8 mma k-chunks

// smem layout (ushort units for the bf16 region)
#define A_HI_OFF 0
#define A_LO_OFF (TOKCTA * ASTR)                 // 8704
#define B_HI_OFF (2 * TOKCTA * ASTR)             // 17408
#define B_LO_OFF (B_HI_OFF + 24 * BSTR)          // 20672
#define SM_USHORTS (B_LO_OFF + 24 * BSTR)        // 23936 ushorts = 47872 B
#define SSQ_STRIDE 33
#define SMEM_TC_BYTES (SM_USHORTS * 2 + TOKCTA * SSQ_STRIDE * 4 + TOKCTA * 4)  // 56576 B

// ---------------- scratch ----------------
__device__ __align__(16) unsigned short g_hi[AA * 24 * NC];         // phi hi (bf16), [a][k][d]
__device__ __align__(16) unsigned short g_lo[AA * 24 * NC];         // phi lo residual
__device__ __align__(16) float part_buf[KSPLIT * BB * TT * PARTW];  // 29.4 MB
__device__ __align__(16) float W_buf[BB * TT * 16];

// ---------------- helpers ----------------
__device__ __forceinline__ void cp16(uint32_t dst, const void* src) {
    asm volatile("cp.async.cg.shared.global [%0], [%1], 16;" :: "r"(dst), "l"(src));
}
__device__ __forceinline__ void mma_bf16(float* c, uint32_t a0, uint32_t a1, uint32_t a2,
                                         uint32_t a3, uint32_t b0, uint32_t b1) {
    asm volatile("mma.sync.aligned.m16n8k16.row.col.f32.bf16.bf16.f32 "
                 "{%0,%1,%2,%3}, {%4,%5,%6,%7}, {%8,%9}, {%0,%1,%2,%3};"
                 : "+f"(c[0]), "+f"(c[1]), "+f"(c[2]), "+f"(c[3])
                 : "r"(a0), "r"(a1), "r"(a2), "r"(a3), "r"(b0), "r"(b1));
}
__device__ __forceinline__ uint32_t cvt_bf16x2(float hi, float lo) {
    uint32_t d;
    asm("cvt.rn.bf16x2.f32 %0, %1, %2;" : "=r"(d) : "f"(hi), "f"(lo));
    return d;
}

// ---------------- kernel 1: fold v2 — coalesced, thread per (a, d-pair) ----------------
__global__ void fold_tc(const float* __restrict__ wnorm,
                        const float* __restrict__ ppre, const float* __restrict__ ppost,
                        const float* __restrict__ pres,
                        const float* __restrict__ apre, const float* __restrict__ apost,
                        const float* __restrict__ ares) {
    const int idx = blockIdx.x * 128 + threadIdx.x;   // 0..16383
    const int a = idx >> 11;
    const int d = (idx & 2047) * 2;
    const int ad0 = a * NC + d, ad1 = ad0 + 1;
    const float w0 = wnorm[ad0], w1 = wnorm[ad1];
    const float ap = apre[a], ao = apost[a], ar = ares[a];

    auto emit = [&](int k, float v0, float v1) {
        __nv_bfloat16 h0 = __float2bfloat16(v0);
        __nv_bfloat16 h1 = __float2bfloat16(v1);
        uint32_t hi = (uint32_t)__bfloat16_as_ushort(h0)
                    | ((uint32_t)__bfloat16_as_ushort(h1) << 16);
        uint32_t lo = cvt_bf16x2(v1 - __bfloat162float(h1), v0 - __bfloat162float(h0));
        size_t o = (size_t)(a * 24 + k) * NC + d;
        *(uint32_t*)(g_hi + o) = hi;
        *(uint32_t*)(g_lo + o) = lo;
    };

    float4 p0, p1;
    p0 = ((const float4*)ppre)[ad0]; p1 = ((const float4*)ppre)[ad1];
    emit(0, ap * w0 * p0.x, ap * w1 * p1.x);
    emit(1, ap * w0 * p0.y, ap * w1 * p1.y);
    emit(2, ap * w0 * p0.z, ap * w1 * p1.z);
    emit(3, ap * w0 * p0.w, ap * w1 * p1.w);
    p0 = ((const float4*)ppost)[ad0]; p1 = ((const float4*)ppost)[ad1];
    emit(4, ao * w0 * p0.x, ao * w1 * p1.x);
    emit(5, ao * w0 * p0.y, ao * w1 * p1.y);
    emit(6, ao * w0 * p0.z, ao * w1 * p1.z);
    emit(7, ao * w0 * p0.w, ao * w1 * p1.w);
#pragma unroll
    for (int q = 0; q < 4; ++q) {
        p0 = ((const float4*)pres)[(size_t)ad0 * 4 + q];
        p1 = ((const float4*)pres)[(size_t)ad1 * 4 + q];
        emit(8 + 4 * q,     ar * w0 * p0.x, ar * w1 * p1.x);
        emit(9 + 4 * q,     ar * w0 * p0.y, ar * w1 * p1.y);
        emit(10 + 4 * q,    ar * w0 * p0.z, ar * w1 * p1.z);
        emit(11 + 4 * q,    ar * w0 * p0.w, ar * w1 * p1.w);
    }
}

// ---------------- kernel 2: logits via mma.sync bf16 hi/lo, v3 (no shuffles) ----------------
// grid = 4096: blockIdx.x = tt*KSPLIT + ks. 128 threads = 4 warps; warp w -> rows w*16..w*16+15.
__global__ void __launch_bounds__(128, 4)
logits_tc(const float* __restrict__ x, const int* __restrict__ aidx) {
    extern __shared__ __align__(16) unsigned short sm[];
    unsigned short* Ah = sm + A_HI_OFF;
    unsigned short* Al = sm + A_LO_OFF;
    unsigned short* Bh = sm + B_HI_OFF;
    unsigned short* Bl = sm + B_LO_OFF;
    float* ssq_sm = (float*)(sm + SM_USHORTS);          // [64][33]
    float* ssq_fin = ssq_sm + TOKCTA * SSQ_STRIDE;      // [64]

    const int tid = threadIdx.x;
    const int ks = blockIdx.x & (KSPLIT - 1);
    const int tt = blockIdx.x >> 5;               // 0..127
    const int t0 = tt * TOKCTA;
    const int aid = aidx[t0 >> 11];
    const int warp = tid >> 5, lane = tid & 31;

    // ---- B (phi hi/lo) via cp.async: 24 rows x 128 els ----
    uint32_t sb = (uint32_t)__cvta_generic_to_shared(sm);
#pragma unroll
    for (int i = 0; i < 3; ++i) {
        int f = i * 128 + tid;                    // 0..383
        int n = f >> 4, c = f & 15;
        size_t src = (size_t)(aid * 24 + n) * NC + ks * DK + c * 8;
        cp16(sb + (B_HI_OFF + n * BSTR + c * 8) * 2, g_hi + src);
        cp16(sb + (B_LO_OFF + n * BSTR + c * 8) * 2, g_lo + src);
    }
    asm volatile("cp.async.commit_group;");

    // ---- A: coalesced x load, truncation split, ssq partials to smem (NO shuffles) ----
    {
        const float* xbase = x + (size_t)t0 * NC + ks * DK;
#pragma unroll 4
        for (int r = 0; r < 16; ++r) {
            const int row = warp * 16 + r;
            float4 v = *((const float4*)(xbase + (size_t)row * NC) + lane);
            float ps = v.x * v.x + v.y * v.y + v.z * v.z + v.w * v.w;

            uint32_t u0 = __float_as_uint(v.x), u1 = __float_as_uint(v.y);
            uint32_t u2 = __float_as_uint(v.z), u3 = __float_as_uint(v.w);
            uint32_t h01 = __byte_perm(u0, u1, 0x7632);
            uint32_t h23 = __byte_perm(u2, u3, 0x7632);
            float f0 = __uint_as_float(u0 & 0xffff0000u);
            float f1 = __uint_as_float(u1 & 0xffff0000u);
            float f2 = __uint_as_float(u2 & 0xffff0000u);
            float f3 = __uint_as_float(u3 & 0xffff0000u);
            uint32_t l01 = cvt_bf16x2(v.y - f1, v.x - f0);
            uint32_t l23 = cvt_bf16x2(v.w - f3, v.z - f2);

            *(uint2*)(Ah + row * ASTR + lane * 4) = make_uint2(h01, h23);
            *(uint2*)(Al + row * ASTR + lane * 4) = make_uint2(l01, l23);
            ssq_sm[row * SSQ_STRIDE + lane] = ps;
        }
    }

    asm volatile("cp.async.wait_group 0;");
    __syncthreads();

    // ---- ssq reduce: 64 threads, one row each ----
    if (tid < TOKCTA) {
        const float* rp = ssq_sm + tid * SSQ_STRIDE;
        float s = 0.0f;
#pragma unroll 8
        for (int l = 0; l < 32; ++l) s += rp[l];
        ssq_fin[tid] = s;
    }

    // ---- mma mainloop (fragment mapping verified in R12) ----
    const int g = lane >> 2, t = lane & 3;
    const int grow = warp * 16;

    float acc[3][4];
#pragma unroll
    for (int nt = 0; nt < 3; ++nt)
#pragma unroll
        for (int q = 0; q < 4; ++q) acc[nt][q] = 0.0f;

    const unsigned short* ArH  = Ah + (grow + g) * ASTR + 2 * t;
    const unsigned short* ArH8 = ArH + 8 * ASTR;
    const unsigned short* ArL  = Al + (grow + g) * ASTR + 2 * t;
    const unsigned short* ArL8 = ArL + 8 * ASTR;

#pragma unroll
    for (int kc = 0; kc < NKC; ++kc) {
        const int k0 = kc * 16;
        uint32_t ah0 = *(const uint32_t*)(ArH  + k0);
        uint32_t ah1 = *(const uint32_t*)(ArH8 + k0);
        uint32_t ah2 = *(const uint32_t*)(ArH  + k0 + 8);
        uint32_t ah3 = *(const uint32_t*)(ArH8 + k0 + 8);
        uint32_t al0 = *(const uint32_t*)(ArL  + k0);
        uint32_t al1 = *(const uint32_t*)(ArL8 + k0);
        uint32_t al2 = *(const uint32_t*)(ArL  + k0 + 8);
        uint32_t al3 = *(const uint32_t*)(ArL8 + k0 + 8);
#pragma unroll
        for (int nt = 0; nt < 3; ++nt) {
            const unsigned short* brh = Bh + (nt * 8 + g) * BSTR + 2 * t + k0;
            const unsigned short* brl = Bl + (nt * 8 + g) * BSTR + 2 * t + k0;
            uint32_t bh0 = *(const uint32_t*)(brh);
            uint32_t bh1 = *(const uint32_t*)(brh + 8);
            uint32_t bl0 = *(const uint32_t*)(brl);
            uint32_t bl1 = *(const uint32_t*)(brl + 8);
            mma_bf16(acc[nt], ah0, ah1, ah2, ah3, bh0, bh1);   // hi*hi
            mma_bf16(acc[nt], ah0, ah1, ah2, ah3, bl0, bl1);   // hi*lo
            mma_bf16(acc[nt], al0, al1, al2, al3, bh0, bh1);   // lo*hi
        }
    }

    __syncthreads();   // ssq_fin visible to all

    // ---- epilogue: D rows = tokens directly ----
    const int r1 = t0 + grow + g, r2 = r1 + 8;
    float* p1 = part_buf + ((size_t)ks * (BB * TT) + r1) * PARTW;
    float* p2 = part_buf + ((size_t)ks * (BB * TT) + r2) * PARTW;
#pragma unroll
    for (int nt = 0; nt < 3; ++nt) {
        *(float2*)(p1 + nt * 8 + 2 * t) = make_float2(acc[nt][0], acc[nt][1]);
        *(float2*)(p2 + nt * 8 + 2 * t) = make_float2(acc[nt][2], acc[nt][3]);
    }
    if (t == 0) {
        p1[24] = ssq_fin[grow + g];
        p2[24] = ssq_fin[grow + g + 8];
    }
}

// ---------------- kernel 3: finalize (reduce 32 splits, sinkhorn -> W) ----------------
__global__ void finalize_k(const float* __restrict__ bpre, const float* __restrict__ bpost,
                           const float* __restrict__ bres, const int* __restrict__ aidx) {
    const int t = blockIdx.x * 128 + threadIdx.x;
    const int aid = aidx[t >> 11];

    float a[24];
#pragma unroll
    for (int k = 0; k < 24; ++k) a[k] = 0.0f;
    float ssq = 0.0f;
#pragma unroll 8
    for (int ks = 0; ks < KSPLIT; ++ks) {
        const float4* p = (const float4*)(part_buf + ((size_t)ks * (BB * TT) + t) * PARTW);
#pragma unroll
        for (int q = 0; q < 6; ++q) {
            float4 v = p[q];
            a[q * 4 + 0] += v.x; a[q * 4 + 1] += v.y;
            a[q * 4 + 2] += v.z; a[q * 4 + 3] += v.w;
        }
        ssq += p[6].x;
    }
    float rinv = rsqrtf(ssq * (1.0f / 4096.0f) + EPS_);

    float hpre[4], hpost[4];
#pragma unroll
    for (int n = 0; n < 4; ++n)
        hpre[n] = 1.0f / (1.0f + expf(-(a[n] * rinv + bpre[aid * 4 + n])));
#pragma unroll
    for (int n = 0; n < 4; ++n)
        hpost[n] = 2.0f / (1.0f + expf(-(a[4 + n] * rinv + bpost[aid * 4 + n])));

    float m[16];
#pragma unroll
    for (int ij = 0; ij < 16; ++ij)
        m[ij] = expf(a[8 + ij] * rinv + bres[aid * 16 + ij]);

    for (int it = 0; it < SINK_ITERS; ++it) {
#pragma unroll
        for (int i = 0; i < 4; ++i) {
            float r = 1.0f / (m[i * 4] + m[i * 4 + 1] + m[i * 4 + 2] + m[i * 4 + 3]);
            m[i * 4] *= r; m[i * 4 + 1] *= r; m[i * 4 + 2] *= r; m[i * 4 + 3] *= r;
        }
#pragma unroll
        for (int j = 0; j < 4; ++j) {
            float r = 1.0f / (m[j] + m[4 + j] + m[8 + j] + m[12 + j]);
            m[j] *= r; m[4 + j] *= r; m[8 + j] *= r; m[12 + j] *= r;
        }
    }

    float4* wd = (float4*)(W_buf + (size_t)t * 16);
#pragma unroll
    for (int i = 0; i < 4; ++i)
        wd[i] = make_float4(m[i * 4 + 0] + hpost[i] * hpre[0],
                            m[i * 4 + 1] + hpost[i] * hpre[1],
                            m[i * 4 + 2] + hpost[i] * hpre[2],
                            m[i * 4 + 3] + hpost[i] * hpre[3]);
}

// ---------------- kernel 4: out[token] = W @ x[token] ----------------
__global__ void out_k(const float* __restrict__ x, float* __restrict__ out) {
    const int token = (BB * TT - 1) - blockIdx.x;
    __shared__ float sW[16];
    if (threadIdx.x < 16) sW[threadIdx.x] = W_buf[(size_t)token * 16 + threadIdx.x];
    __syncthreads();
    const float4* xr = (const float4*)(x + (size_t)token * NC);
    float4* orow = (float4*)(out + (size_t)token * NC);
    const int c = threadIdx.x;
    float4 xv0 = xr[c], xv1 = xr[256 + c], xv2 = xr[512 + c], xv3 = xr[768 + c];
#pragma unroll
    for (int i = 0; i < 4; ++i) {
        float w0 = sW[i * 4], w1 = sW[i * 4 + 1], w2 = sW[i * 4 + 2], w3 = sW[i * 4 + 3];
        float4 o;
        o.x = w0 * xv0.x + w1 * xv1.x + w2 * xv2.x + w3 * xv3.x;
        o.y = w0 * xv0.y + w1 * xv1.y + w2 * xv2.y + w3 * xv3.y;
        o.z = w0 * xv0.z + w1 * xv1.z + w2 * xv2.z + w3 * xv3.z;
        o.w = w0 * xv0.w + w1 * xv1.w + w2 * xv2.w + w3 * xv3.w;
        orow[i * 256 + c] = o;
    }
}

// ---------------- launch ----------------
extern "C" void kernel_launch(void* const* d_in, const int* in_sizes, int n_in,
                              void* d_out, int out_size) {
    const float* x     = (const float*)d_in[0];
    const float* wnorm = (const float*)d_in[1];
    const float* ppre  = (const float*)d_in[2];
    const float* ppost = (const float*)d_in[3];
    const float* pres  = (const float*)d_in[4];
    const float* bpre  = (const float*)d_in[5];
    const float* bpost = (const float*)d_in[6];
    const float* bres  = (const float*)d_in[7];
    const float* apre  = (const float*)d_in[8];
    const float* apost = (const float*)d_in[9];
    const float* ares  = (const float*)d_in[10];
    const int*   aidx  = (const int*)d_in[11];
    float* out = (float*)d_out;

    cudaFuncSetAttribute(logits_tc, cudaFuncAttributeMaxDynamicSharedMemorySize, SMEM_TC_BYTES);

    fold_tc<<<AA * NC / 2 / 128, 128>>>(wnorm, ppre, ppost, pres, apre, apost, ares);
    logits_tc<<<NTILES * KSPLIT, 128, SMEM_TC_BYTES>>>(x, aidx);
    finalize_k<<<BB * TT / 128, 128>>>(bpre, bpost, bres, aidx);
    out_k<<<BB * TT, 256>>>(x, out);
}